// round 4
// baseline (speedup 1.0000x reference)
#include <cuda_runtime.h>
#include <cstdint>
#include <math.h>

#define NB 8
#define NT 2048
#define NC 512
#define SCALE 0.04419417382415922f   // 1/sqrt(512)

// ---------------- scratch (__device__ globals; allocation-free rule) --------
// bf16 operand arrays stored as uint16_t
__device__ __align__(256) uint16_t g_xh [NB * NT * NC];
__device__ __align__(256) uint16_t g_xl [NB * NT * NC];
__device__ __align__(256) uint16_t g_wTh[3 * NC * NC];
__device__ __align__(256) uint16_t g_wTl[3 * NC * NC];
__device__ __align__(256) uint16_t g_qh [NB * NT * NC];
__device__ __align__(256) uint16_t g_ql [NB * NT * NC];
__device__ __align__(256) uint16_t g_kh [NB * NT * NC];
__device__ __align__(256) uint16_t g_kl [NB * NT * NC];
__device__ __align__(256) uint16_t g_vTh[NB * NT * NC];   // [b][c][t]
__device__ __align__(256) uint16_t g_vTl[NB * NT * NC];
__device__ __align__(256) uint16_t g_Ph [(size_t)NB * NT * NT]; // P' [b][t][s]
__device__ __align__(256) uint16_t g_Pl [(size_t)NB * NT * NT];
__device__ __align__(256) float    g_v  [NB * NT * NC];   // fp32 v [b][t][c]
__device__ __align__(256) float    g_lg [(size_t)NB * NT * NT]; // lgT [b][s][t]
__device__ float g_mx [NB * NT];
__device__ float g_inv[NB * NT];

// ---------------- helpers ---------------------------------------------------
__device__ __forceinline__ uint32_t smem_u32(const void* p) {
    uint32_t a;
    asm("{ .reg .u64 t; cvta.to.shared.u64 t, %1; cvt.u32.u64 %0, t; }" : "=r"(a) : "l"(p));
    return a;
}
__device__ __forceinline__ uint32_t cvt2bf(float hi_, float lo_) {
    // low halfword = bf16(lo_), high halfword = bf16(hi_)
    uint32_t r;
    asm("cvt.rn.satfinite.bf16x2.f32 %0, %1, %2;" : "=r"(r) : "f"(hi_), "f"(lo_));
    return r;
}
__device__ __forceinline__ uint16_t bf16of(float x) { return (uint16_t)cvt2bf(0.f, x); }
__device__ __forceinline__ float fofbf(uint16_t h) { return __uint_as_float((uint32_t)h << 16); }

__device__ __forceinline__ void mma_bf16(float* c, const uint32_t* a, const uint32_t* b) {
    asm volatile(
        "mma.sync.aligned.m16n8k16.row.col.f32.bf16.bf16.f32 "
        "{%0,%1,%2,%3}, {%4,%5,%6,%7}, {%8,%9}, {%0,%1,%2,%3};"
        : "+f"(c[0]), "+f"(c[1]), "+f"(c[2]), "+f"(c[3])
        : "r"(a[0]), "r"(a[1]), "r"(a[2]), "r"(a[3]), "r"(b[0]), "r"(b[1]));
}
__device__ __forceinline__ void cp8(uint32_t dst, const void* src) {
    asm volatile("cp.async.ca.shared.global [%0], [%1], 8;" :: "r"(dst), "l"(src));
}
#define CP_COMMIT() asm volatile("cp.async.commit_group;" ::: "memory")
#define CP_WAIT(N)  asm volatile("cp.async.wait_group %0;" :: "n"(N) : "memory")

// split a pair (a -> element n, b -> element n+1) into hi/lo bf16 and store
__device__ __forceinline__ void split2(uint16_t* ch, uint16_t* cl, float a, float b) {
    const uint32_t h = cvt2bf(b, a);
    const float ha = __uint_as_float(h << 16);
    const float hb = __uint_as_float(h & 0xffff0000u);
    const uint32_t l = cvt2bf(b - hb, a - ha);
    *(uint32_t*)ch = h;
    *(uint32_t*)cl = l;
}

// ---------------------------------------------------------------------------
// bf16 split-precision GEMM via mma.sync (HMMA), cp.async 4-stage pipeline.
//   D[m][n] = sum_k (Ah+Al)[m][k] * (Bh+Bl)[n][k]   (3 MMA terms)
// CTA tile 128x128, BK=32, 256 threads, warp tile 64x32.
// Stage = Ah|Al|Bh|Bl, 8KB each (128 rows x 64B, 8B-word XOR swizzle).
// CSKIP: skip tile if n0+127 < m0.  CKLIM: kend = m0+128.
// EPI16: write C as hi/lo bf16 pair arrays (with optional bias) else fp32.
// ---------------------------------------------------------------------------
#define NSTG 4
template<bool BIAS, bool CSKIP, bool CKLIM, bool EPI16>
__global__ __launch_bounds__(256, 1)
void gemm_bf(const uint16_t* __restrict__ Ahg, const uint16_t* __restrict__ Alg,
             const uint16_t* __restrict__ Bhg, const uint16_t* __restrict__ Blg,
             const float* __restrict__ bias, float* __restrict__ Cg,
             uint16_t* __restrict__ Chg, uint16_t* __restrict__ Clg,
             int lda, int ldb, int ldc, int Ktot,
             size_t sA, size_t sB, size_t sC)
{
    extern __shared__ char smem[];
    const int m0 = blockIdx.y * 128;
    const int n0 = blockIdx.x * 128;
    if (CSKIP && (n0 + 127) < m0) return;

    const uint16_t* Ah = Ahg + (size_t)blockIdx.z * sA;
    const uint16_t* Al = Alg + (size_t)blockIdx.z * sA;
    const uint16_t* Bh = Bhg + (size_t)blockIdx.z * sB;
    const uint16_t* Bl = Blg + (size_t)blockIdx.z * sB;

    const int tid = threadIdx.x;
    const int lane = tid & 31;
    const int wid = tid >> 5;
    const int warp_m = (wid & 1) * 64;
    const int warp_n = (wid >> 1) * 32;
    const int g  = lane >> 2;
    const int tg = lane & 3;
    const uint32_t smem_u = smem_u32(smem);

    // fragment smem column offsets (swizzle folded in)
    uint32_t colOff[4];
    {
        const uint32_t w0 = tg >> 1, sub4 = (tg & 1) * 4;
#pragma unroll
        for (int j = 0; j < 4; j++)
            colOff[j] = (((w0 + 2 * j) ^ (uint32_t)g) << 3) + sub4;
    }
    uint32_t aoff0[4], aoff1[4], boff[4];
#pragma unroll
    for (int mt = 0; mt < 4; mt++) {
        aoff0[mt] = (uint32_t)(warp_m + mt * 16 + g) * 64;
        aoff1[mt] = aoff0[mt] + 8 * 64;
    }
#pragma unroll
    for (int nt = 0; nt < 4; nt++)
        boff[nt] = (uint32_t)(warp_n + nt * 8 + g) * 64;

    // loader indices: word w (8B = 4 bf16), rows r0+32i
    const int lw = tid & 7;
    const int lr = tid >> 3;

    float acc[4][4][4];
#pragma unroll
    for (int mt = 0; mt < 4; mt++)
#pragma unroll
        for (int nt = 0; nt < 4; nt++)
#pragma unroll
            for (int r = 0; r < 4; r++) acc[mt][nt][r] = 0.f;

    const int kend = CKLIM ? min(Ktot, m0 + 128) : Ktot;
    const int nch = kend >> 5;

    // ---- cp.async stage loader ----
    auto load_stage = [&](int slot, int chunk) {
        const uint32_t sbase = smem_u + (uint32_t)slot * 32768u;
        const int k0 = chunk << 5;
#pragma unroll
        for (int i = 0; i < 4; i++) {
            const int r = lr + i * 32;
            const uint32_t off = (uint32_t)r * 64 + ((uint32_t)(lw ^ (r & 7)) << 3);
            const size_t aoffg = (size_t)(m0 + r) * lda + k0 + lw * 4;
            const size_t boffg = (size_t)(n0 + r) * ldb + k0 + lw * 4;
            cp8(sbase + off,         Ah + aoffg);
            cp8(sbase + 8192 + off,  Al + aoffg);
            cp8(sbase + 16384 + off, Bh + boffg);
            cp8(sbase + 24576 + off, Bl + boffg);
        }
    };

    int issued = 0;
    for (; issued < NSTG - 1 && issued < nch; issued++) {
        load_stage(issued, issued);
        CP_COMMIT();
    }

    for (int c = 0; c < nch; c++) {
        if (issued < nch) {
            load_stage(issued & (NSTG - 1), issued);
            issued++;
        }
        CP_COMMIT();
        CP_WAIT(NSTG - 2);
        __syncthreads();

        const char* base = smem + (size_t)(c & (NSTG - 1)) * 32768;
#pragma unroll
        for (int ks = 0; ks < 2; ks++) {
            const uint32_t co0 = colOff[2 * ks];
            const uint32_t co1 = colOff[2 * ks + 1];
            uint32_t ah[4][4], al[4][4], bh[4][2], bl[4][2];
#pragma unroll
            for (int mt = 0; mt < 4; mt++) {
                ah[mt][0] = *(const uint32_t*)(base + aoff0[mt] + co0);
                ah[mt][1] = *(const uint32_t*)(base + aoff1[mt] + co0);
                ah[mt][2] = *(const uint32_t*)(base + aoff0[mt] + co1);
                ah[mt][3] = *(const uint32_t*)(base + aoff1[mt] + co1);
                al[mt][0] = *(const uint32_t*)(base + 8192 + aoff0[mt] + co0);
                al[mt][1] = *(const uint32_t*)(base + 8192 + aoff1[mt] + co0);
                al[mt][2] = *(const uint32_t*)(base + 8192 + aoff0[mt] + co1);
                al[mt][3] = *(const uint32_t*)(base + 8192 + aoff1[mt] + co1);
            }
#pragma unroll
            for (int nt = 0; nt < 4; nt++) {
                bh[nt][0] = *(const uint32_t*)(base + 16384 + boff[nt] + co0);
                bh[nt][1] = *(const uint32_t*)(base + 16384 + boff[nt] + co1);
                bl[nt][0] = *(const uint32_t*)(base + 24576 + boff[nt] + co0);
                bl[nt][1] = *(const uint32_t*)(base + 24576 + boff[nt] + co1);
            }
#pragma unroll
            for (int mt = 0; mt < 4; mt++)
#pragma unroll
                for (int nt = 0; nt < 4; nt++) {
                    mma_bf16(acc[mt][nt], ah[mt], bh[nt]);
                    mma_bf16(acc[mt][nt], ah[mt], bl[nt]);
                    mma_bf16(acc[mt][nt], al[mt], bh[nt]);
                }
        }
        __syncthreads();
    }

    // ---- epilogue ----
#pragma unroll
    for (int mt = 0; mt < 4; mt++) {
        const int m = m0 + warp_m + mt * 16 + g;
#pragma unroll
        for (int nt = 0; nt < 4; nt++) {
            const int n = n0 + warp_n + nt * 8 + tg * 2;
            float v00 = acc[mt][nt][0], v01 = acc[mt][nt][1];
            float v10 = acc[mt][nt][2], v11 = acc[mt][nt][3];
            if (BIAS) {
                const float b0 = bias[n], b1 = bias[n + 1];
                v00 += b0; v01 += b1;
                v10 += b0; v11 += b1;
            }
            if (EPI16) {
                uint16_t* ch = Chg + (size_t)blockIdx.z * sC + (size_t)m * ldc + n;
                uint16_t* cl = Clg + (size_t)blockIdx.z * sC + (size_t)m * ldc + n;
                split2(ch, cl, v00, v01);
                split2(ch + (size_t)8 * ldc, cl + (size_t)8 * ldc, v10, v11);
            } else {
                float* crow = Cg + (size_t)blockIdx.z * sC + (size_t)m * ldc + n;
                *(float2*)crow = make_float2(v00, v01);
                *(float2*)(crow + (size_t)8 * ldc) = make_float2(v10, v11);
            }
        }
    }
}

// ---------------------------------------------------------------------------
// elementwise fp32 -> bf16 hi/lo (vectorized by 4)
// ---------------------------------------------------------------------------
__global__ void cvt_pair(const float4* __restrict__ in, uint2* __restrict__ h4,
                         uint2* __restrict__ l4, int n4)
{
    const int i = blockIdx.x * blockDim.x + threadIdx.x;
    if (i >= n4) return;
    const float4 v = in[i];
    const uint32_t h01 = cvt2bf(v.y, v.x);
    const uint32_t h23 = cvt2bf(v.w, v.z);
    const float hx = __uint_as_float(h01 << 16);
    const float hy = __uint_as_float(h01 & 0xffff0000u);
    const float hz = __uint_as_float(h23 << 16);
    const float hw = __uint_as_float(h23 & 0xffff0000u);
    const uint32_t l01 = cvt2bf(v.y - hy, v.x - hx);
    const uint32_t l23 = cvt2bf(v.w - hw, v.z - hz);
    h4[i] = make_uint2(h01, h23);
    l4[i] = make_uint2(l01, l23);
}

// 512x512 transpose + split: WT[n][k] = W[k][n] as bf16 hi/lo
__global__ void trans512cv(const float* __restrict__ W,
                           uint16_t* __restrict__ WTh, uint16_t* __restrict__ WTl)
{
    __shared__ float tile[32][33];
    const int tx = threadIdx.x & 31, ty = threadIdx.x >> 5;
    const int c0 = blockIdx.x * 32, r0 = blockIdx.y * 32;
#pragma unroll
    for (int r = 0; r < 4; r++)
        tile[ty + r * 8][tx] = W[(size_t)(r0 + ty + r * 8) * NC + c0 + tx];
    __syncthreads();
#pragma unroll
    for (int r = 0; r < 4; r++) {
        const float v = tile[tx][ty + r * 8];
        const uint16_t h = bf16of(v);
        const uint16_t l = bf16of(v - fofbf(h));
        const size_t o = (size_t)(c0 + ty + r * 8) * NC + r0 + tx;
        WTh[o] = h;
        WTl[o] = l;
    }
}

// v[b][t][c] fp32 -> vT[b][c][t] bf16 hi/lo
__global__ void trans_btc_cv(const float* __restrict__ in,
                             uint16_t* __restrict__ oh, uint16_t* __restrict__ ol)
{
    __shared__ float tile[32][33];
    const int c0 = blockIdx.x * 32, t0 = blockIdx.y * 32, b = blockIdx.z;
    const float* ip = in + (size_t)b * NT * NC;
    const int tx = threadIdx.x & 31, ty = threadIdx.x >> 5;
#pragma unroll
    for (int r = 0; r < 4; r++)
        tile[ty + r * 8][tx] = ip[(size_t)(t0 + ty + r * 8) * NC + c0 + tx];
    __syncthreads();
#pragma unroll
    for (int r = 0; r < 4; r++) {
        const float v = tile[tx][ty + r * 8];
        const uint16_t h = bf16of(v);
        const uint16_t l = bf16of(v - fofbf(h));
        const size_t o = (size_t)b * NT * NC + (size_t)(c0 + ty + r * 8) * NT + t0 + tx;
        oh[o] = h;
        ol[o] = l;
    }
}

// ---------------------------------------------------------------------------
// softmax pass 1: per key-column s, reduce over t >= s -> mx[s], 1/sum
// ---------------------------------------------------------------------------
__global__ void softmax_p1(const float* __restrict__ lg,
                           float* __restrict__ mx, float* __restrict__ inv)
{
    const int s = blockIdx.x, b = blockIdx.y;
    const float* row = lg + ((size_t)b * NT + s) * NT;
    __shared__ float red[256];
    const int tid = threadIdx.x;

    float lmax = -3.4e38f;
    for (int t = s + tid; t < NT; t += 256) lmax = fmaxf(lmax, row[t]);
    red[tid] = lmax;
    __syncthreads();
    for (int off = 128; off > 0; off >>= 1) {
        if (tid < off) red[tid] = fmaxf(red[tid], red[tid + off]);
        __syncthreads();
    }
    const float m = red[0] * SCALE;
    __syncthreads();

    float lsum = 0.f;
    for (int t = s + tid; t < NT; t += 256) lsum += __expf(row[t] * SCALE - m);
    red[tid] = lsum;
    __syncthreads();
    for (int off = 128; off > 0; off >>= 1) {
        if (tid < off) red[tid] += red[tid + off];
        __syncthreads();
    }
    if (tid == 0) {
        mx[b * NT + s]  = m;
        inv[b * NT + s] = 1.f / red[0];
    }
}

// ---------------------------------------------------------------------------
// softmax pass 2: exp + normalize + transpose -> P'[b][t][s] bf16 hi/lo
// ---------------------------------------------------------------------------
__global__ void softmax_p2(const float* __restrict__ lg, const float* __restrict__ mx,
                           const float* __restrict__ inv,
                           uint16_t* __restrict__ Ph, uint16_t* __restrict__ Pl)
{
    const int ti = blockIdx.x, si = blockIdx.y, b = blockIdx.z;
    if (si * 32 >= ti * 32 + 128) return;   // never read by the read-GEMM
    __shared__ float tile[32][33];
    const int tx = threadIdx.x & 31, ty = threadIdx.x >> 5;
    const int t = ti * 32 + tx;
#pragma unroll
    for (int r = 0; r < 4; r++) {
        const int s = si * 32 + ty + r * 8;
        float p = 0.f;
        if (t >= s) {
            const float val = lg[((size_t)b * NT + s) * NT + t];
            p = __expf(val * SCALE - mx[b * NT + s]) * inv[b * NT + s];
        }
        tile[ty + r * 8][tx] = p;
    }
    __syncthreads();
    const int s2 = si * 32 + tx;
#pragma unroll
    for (int r = 0; r < 4; r++) {
        const int t2 = ti * 32 + ty + r * 8;
        const float v = tile[tx][ty + r * 8];
        const uint16_t h = bf16of(v);
        const uint16_t l = bf16of(v - fofbf(h));
        const size_t o = ((size_t)b * NT + t2) * NT + s2;
        Ph[o] = h;
        Pl[o] = l;
    }
}

// out[..., 0:512] = x
__global__ void copy_x_k(const float4* __restrict__ x4, float4* __restrict__ out4)
{
    const size_t i = (size_t)blockIdx.x * blockDim.x + threadIdx.x;
    const size_t row = i >> 7;
    const size_t col = i & 127;
    out4[row * 256 + col] = x4[i];
}

// ---------------------------------------------------------------------------
extern "C" void kernel_launch(void* const* d_in, const int* in_sizes, int n_in,
                              void* d_out, int out_size)
{
    const float* x  = (const float*)d_in[0];
    const float* Wq = (const float*)d_in[1];
    const float* bq = (const float*)d_in[2];
    const float* Wk = (const float*)d_in[3];
    const float* bk = (const float*)d_in[4];
    const float* Wv = (const float*)d_in[5];
    const float* bv = (const float*)d_in[6];
    float* out = (float*)d_out;

    uint16_t *xh, *xl, *wTh, *wTl, *qh, *ql, *kh, *kl, *vTh, *vTl, *Ph, *Pl;
    float *v, *lg, *mx, *inv;
    cudaGetSymbolAddress((void**)&xh,  g_xh);
    cudaGetSymbolAddress((void**)&xl,  g_xl);
    cudaGetSymbolAddress((void**)&wTh, g_wTh);
    cudaGetSymbolAddress((void**)&wTl, g_wTl);
    cudaGetSymbolAddress((void**)&qh,  g_qh);
    cudaGetSymbolAddress((void**)&ql,  g_ql);
    cudaGetSymbolAddress((void**)&kh,  g_kh);
    cudaGetSymbolAddress((void**)&kl,  g_kl);
    cudaGetSymbolAddress((void**)&vTh, g_vTh);
    cudaGetSymbolAddress((void**)&vTl, g_vTl);
    cudaGetSymbolAddress((void**)&Ph,  g_Ph);
    cudaGetSymbolAddress((void**)&Pl,  g_Pl);
    cudaGetSymbolAddress((void**)&v,   g_v);
    cudaGetSymbolAddress((void**)&lg,  g_lg);
    cudaGetSymbolAddress((void**)&mx,  g_mx);
    cudaGetSymbolAddress((void**)&inv, g_inv);

    const int SMEM = NSTG * 32768;   // 131072
    cudaFuncSetAttribute(gemm_bf<true,  false, false, true >, cudaFuncAttributeMaxDynamicSharedMemorySize, SMEM);
    cudaFuncSetAttribute(gemm_bf<true,  false, false, false>, cudaFuncAttributeMaxDynamicSharedMemorySize, SMEM);
    cudaFuncSetAttribute(gemm_bf<false, true,  false, false>, cudaFuncAttributeMaxDynamicSharedMemorySize, SMEM);
    cudaFuncSetAttribute(gemm_bf<false, false, true,  false>, cudaFuncAttributeMaxDynamicSharedMemorySize, SMEM);

    const size_t strBT  = (size_t)NT * NC;
    const size_t strLG  = (size_t)NT * NT;
    const size_t strOUT = (size_t)NT * (2 * NC);

    // 0) one-shot operand prep: x -> bf16 h/l; W -> transposed bf16 h/l
    cvt_pair<<<(NB * NT * NC / 4 + 255) / 256, 256>>>((const float4*)x, (uint2*)xh, (uint2*)xl, NB * NT * NC / 4);
    trans512cv<<<dim3(16, 16), 256>>>(Wq, wTh + 0 * NC * NC, wTl + 0 * NC * NC);
    trans512cv<<<dim3(16, 16), 256>>>(Wk, wTh + 1 * NC * NC, wTl + 1 * NC * NC);
    trans512cv<<<dim3(16, 16), 256>>>(Wv, wTh + 2 * NC * NC, wTl + 2 * NC * NC);

    // 1) QKV projections (M=16384, N=512, K=512). Q,K epilogue -> bf16 h/l.
    {
        dim3 grid(NC / 128, (NB * NT) / 128, 1);
        gemm_bf<true, false, false, true><<<grid, 256, SMEM>>>(
            xh, xl, wTh + 0 * NC * NC, wTl + 0 * NC * NC, bq,
            nullptr, qh, ql, NC, NC, NC, NC, 0, 0, 0);
        gemm_bf<true, false, false, true><<<grid, 256, SMEM>>>(
            xh, xl, wTh + 1 * NC * NC, wTl + 1 * NC * NC, bk,
            nullptr, kh, kl, NC, NC, NC, NC, 0, 0, 0);
        gemm_bf<true, false, false, false><<<grid, 256, SMEM>>>(
            xh, xl, wTh + 2 * NC * NC, wTl + 2 * NC * NC, bv,
            v, nullptr, nullptr, NC, NC, NC, NC, 0, 0, 0);
    }

    // 1b) v -> vT [b][c][t] bf16 h/l
    trans_btc_cv<<<dim3(NC / 32, NT / 32, NB), 256>>>(v, vTh, vTl);

    // 2) logitsT[b][s][t] = sum_c k[b,s,c] * q[b,t,c]  (causal tile skip)
    {
        dim3 grid(NT / 128, NT / 128, NB);
        gemm_bf<false, true, false, false><<<grid, 256, SMEM>>>(
            kh, kl, qh, ql, nullptr, lg, nullptr, nullptr,
            NC, NC, NT, NC, strBT, strBT, strLG);
    }

    // 3) softmax over t (column softmax) -> P'[b][t][s] bf16 h/l
    softmax_p1<<<dim3(NT, NB), 256>>>(lg, mx, inv);
    softmax_p2<<<dim3(NT / 32, NT / 32, NB), 256>>>(lg, mx, inv, Ph, Pl);

    // 4) read[b][t][v] = sum_s P'[b,t,s] * vT[b,v,s]  -> out[..., 512:1024]
    {
        dim3 grid(NC / 128, NT / 128, NB);
        gemm_bf<false, false, true, false><<<grid, 256, SMEM>>>(
            Ph, Pl, vTh, vTl, nullptr, out + NC, nullptr, nullptr,
            NT, NT, 2 * NC, NT, strLG, (size_t)NC * NT, strOUT);
    }

    // 5) out[..., 0:512] = x
    copy_x_k<<<(NB * NT * NC / 4) / 256, 256>>>((const float4*)x, (float4*)out);
}